// round 2
// baseline (speedup 1.0000x reference)
#include <cuda_runtime.h>

#define NN 35
#define NE 1190
typedef unsigned long long ull;

// ---------------- scratch ----------------
__device__ __align__(16) float g_h1[NN * 256];
__device__ __align__(16) float g_h2[NN * 256];
__device__ __align__(16) float g_h3[NN * 64];
__device__ __align__(16) float g_msg[NE * 256];
__device__ __align__(16) float g_w2q[256 * 7 * 256];   // [i][v(6w+bias)][o]
__device__ __align__(16) float g_w3q[256 * 7 * 64];
__device__ __align__(16) float g_l2t[256 * 256];       // lin2_w^T [i][o]
__device__ __align__(16) float g_l3t[256 * 64];
__device__ __align__(16) float g_ea8[NE * 8];
__device__ int   g_perm[NE];
__device__ int   g_off[NN + 1];
__device__ float g_inv[NN];

// ---------------- f32x2 helpers ----------------
__device__ __forceinline__ ull fma2(ull a, ull b, ull c) {
    ull d; asm("fma.rn.f32x2 %0, %1, %2, %3;" : "=l"(d) : "l"(a), "l"(b), "l"(c));
    return d;
}
__device__ __forceinline__ ull relu2(ull t) {
    unsigned lo, hi;
    asm("mov.b64 {%0, %1}, %2;" : "=r"(lo), "=r"(hi) : "l"(t));
    float fl = fmaxf(__uint_as_float(lo), 0.f);
    float fh = fmaxf(__uint_as_float(hi), 0.f);
    ull r;
    asm("mov.b64 %0, {%1, %2};" : "=l"(r) : "r"(__float_as_uint(fl)), "r"(__float_as_uint(fh)));
    return r;
}
__device__ __forceinline__ float2 u2f(ull t) {
    unsigned lo, hi;
    asm("mov.b64 {%0, %1}, %2;" : "=r"(lo), "=r"(hi) : "l"(t));
    return make_float2(__uint_as_float(lo), __uint_as_float(hi));
}

// ---------------- fused setup: l1-msg | pack2 | pack3 | transposes | ea8 | CSR ----------------
#define B_L1   298
#define B_P2   (B_L1 + 256)
#define B_P3   (B_P2 + 16)
#define B_T2   (B_P3 + 64)
#define B_T3   (B_T2 + 16)
#define B_EA   (B_T3 + 5)
#define B_ALL  (B_EA + 1)

__global__ void __launch_bounds__(256) k_setup(
    const float* __restrict__ x,  const float* __restrict__ ea,
    const int* __restrict__ eidx,
    const float* __restrict__ n1w, const float* __restrict__ n1b,
    const float* __restrict__ n2w, const float* __restrict__ n2b,
    const float* __restrict__ n3w, const float* __restrict__ n3b,
    const float* __restrict__ l2w, const float* __restrict__ l3w)
{
    __shared__ __align__(16) char smbuf[8192];
    int b = blockIdx.x, tid = threadIdx.x;

    if (b < B_L1) {                                      // layer-1 messages
        int e0 = b * 4, o = tid;
        float w[6];
#pragma unroll
        for (int v = 0; v < 6; v++) w[v] = n1w[o * 6 + v];
        float bb = n1b[o];
#pragma unroll
        for (int k = 0; k < 4; k++) {
            int e = e0 + k;
            if (e < NE) {
                float t = bb;
#pragma unroll
                for (int v = 0; v < 6; v++) t = fmaf(w[v], ea[e * 6 + v], t);
                g_msg[e * 256 + o] = x[eidx[e]] * fmaxf(t, 0.f);
            }
        }
    } else if (b < B_P2) {                               // pack nn2 weights
        int i = b - B_L1, o = tid, io = i * 256 + o;
#pragma unroll
        for (int v = 0; v < 6; v++) g_w2q[(i * 7 + v) * 256 + o] = n2w[io * 6 + v];
        g_w2q[(i * 7 + 6) * 256 + o] = n2b[io];
    } else if (b < B_P3) {                               // pack nn3 weights
        int rb = b - B_P2;
#pragma unroll
        for (int r = 0; r < 4; r++) {
            int i = rb * 16 + r * 4 + (tid >> 6), o = tid & 63, io = i * 64 + o;
#pragma unroll
            for (int v = 0; v < 6; v++) g_w3q[(i * 7 + v) * 64 + o] = n3w[io * 6 + v];
            g_w3q[(i * 7 + 6) * 64 + o] = n3b[io];
        }
    } else if (b < B_T2) {                               // transpose lin2 (coalesced tiles)
        float* tile = (float*)smbuf;
        int rb = b - B_P3, bo = (rb & 7) * 32, bi = (rb >> 3) * 32;
        int tx = tid & 31, ty = tid >> 5;
#pragma unroll
        for (int r = 0; r < 4; r++)
            tile[(ty + r * 8) * 33 + tx] = l2w[(bo + ty + r * 8) * 256 + bi + tx];
        __syncthreads();
#pragma unroll
        for (int r = 0; r < 4; r++)
            g_l2t[(bi + ty + r * 8) * 256 + bo + tx] = tile[tx * 33 + ty + r * 8];
    } else if (b < B_T3) {                               // transpose lin3
        float* tile = (float*)smbuf;
        int rb = b - B_T2, bo = (rb & 1) * 32, bi = (rb >> 1) * 32;
        int tx = tid & 31, ty = tid >> 5;
#pragma unroll
        for (int r = 0; r < 4; r++)
            tile[(ty + r * 8) * 33 + tx] = l3w[(bo + ty + r * 8) * 256 + bi + tx];
        __syncthreads();
#pragma unroll
        for (int r = 0; r < 4; r++)
            g_l3t[(bi + ty + r * 8) * 64 + bo + tx] = tile[tx * 33 + ty + r * 8];
    } else if (b < B_EA) {                               // pad edge attrs to 8
        int rb = b - B_T3;
        for (int idx = rb * 256 + tid; idx < NE * 8; idx += 5 * 256) {
            int e = idx >> 3, v = idx & 7;
            g_ea8[idx] = (v < 6) ? ea[e * 6 + v] : 0.f;
        }
    } else {                                             // deterministic CSR by dst
        int* s_dst = (int*)smbuf;                        // NE ints
        int* s_cnt = s_dst + NE;                         // 7*NN
        int* s_off = s_cnt + 7 * NN;                     // NN+1
        for (int e = tid; e < NE; e += 256) s_dst[e] = eidx[NE + e];
        __syncthreads();
        if (tid < 7 * NN) {
            int c = tid / NN, n = tid % NN;
            int lo = c * 170, cnt = 0;
            for (int e = lo; e < lo + 170; e++) cnt += (s_dst[e] == n);
            s_cnt[c * NN + n] = cnt;
        }
        __syncthreads();
        if (tid == 0) {
            int off = 0;
            for (int n = 0; n < NN; n++) {
                s_off[n] = off;
                for (int c = 0; c < 7; c++) {
                    int t = s_cnt[c * NN + n];
                    s_cnt[c * NN + n] = off;
                    off += t;
                }
            }
            s_off[NN] = off;
        }
        __syncthreads();
        if (tid < 7 * NN) {
            int c = tid / NN, n = tid % NN;
            int lo = c * 170, p = s_cnt[c * NN + n];
            for (int e = lo; e < lo + 170; e++)
                if (s_dst[e] == n) g_perm[p++] = e;
        }
        if (tid <= NN) g_off[tid] = s_off[tid];
        if (tid < NN) g_inv[tid] = 1.0f / (float)max(s_off[tid + 1] - s_off[tid], 1);
    }
}

// ---------------- layer 1 aggregate ----------------
__global__ void k_agg1(const float* __restrict__ x, const float* __restrict__ lw,
                       const float* __restrict__ b) {
    int n = blockIdx.x, o = threadIdx.x;
    int j0 = g_off[n], j1 = g_off[n + 1];
    float acc = 0.f;
    for (int j = j0; j < j1; j++) acc += g_msg[g_perm[j] * 256 + o];
    g_h1[n * 256 + o] = fmaxf(fmaf(acc, g_inv[n], fmaf(x[n], lw[o], b[o])), 0.f);
}

// ---------------- heavy message kernel: packed f32x2 over o-pairs ----------------
// 256 thr = 8 warps; warp w owns i in [32w, 32w+32); lane l owns o-pair (oc+2l, oc+2l+1).
template <int ET, int L>
__global__ void __launch_bounds__(256, 2) k_msg(const int* __restrict__ eidx) {
    constexpr int OTOT = (L == 3) ? 64 : 256;
    constexpr int OP = OTOT / 2;
    const float* __restrict__ wq  = (L == 3) ? g_w3q : g_w2q;
    const float* __restrict__ hin = (L == 3) ? g_h2 : g_h1;

    __shared__ float2 xs_sm[ET * 256];                   // duplicated (x,x)
    __shared__ float2 ea_sm[ET * 8];                     // duplicated (a,a)
    __shared__ float2 red[32 * (ET + 1)];
    __shared__ int    s_src[ET];

    int tid = threadIdx.x, lane = tid & 31, w = tid >> 5;
    int e0 = blockIdx.x * ET;
    int oc = blockIdx.y * 64;
    int op = (oc >> 1) + lane;

    if (tid < ET) {
        int ee = e0 + tid; if (ee >= NE) ee = NE - 1;
        s_src[tid] = eidx[ee];
    }
    __syncthreads();
    for (int idx = tid; idx < ET * 8; idx += 256) {
        int e = idx >> 3, ee = e0 + e; if (ee >= NE) ee = NE - 1;
        float a = g_ea8[ee * 8 + (idx & 7)];
        ea_sm[idx] = make_float2(a, a);
    }
    for (int idx = tid; idx < ET * 256; idx += 256) {
        int e = idx >> 8, c = idx & 255;
        float v = hin[s_src[e] * 256 + c];
        xs_sm[idx] = make_float2(v, v);
    }
    __syncthreads();

    const ull* wq2  = (const ull*)wq;
    const ull* xs_u = (const ull*)xs_sm;
    const ull* ea_u = (const ull*)ea_sm;

    ull acc[ET];
#pragma unroll
    for (int e = 0; e < ET; e++) acc[e] = 0ull;

#pragma unroll 1
    for (int itb = 0; itb < 16; itb++) {
        int i0 = w * 32 + itb * 2;
        ull w0[7], w1[7];
        size_t b0 = (size_t)(i0 * 7) * OP + op;
        size_t b1 = (size_t)((i0 + 1) * 7) * OP + op;
#pragma unroll
        for (int v = 0; v < 7; v++) { w0[v] = wq2[b0 + v * OP]; w1[v] = wq2[b1 + v * OP]; }
#pragma unroll
        for (int e = 0; e < ET; e++) {
            const ull* ap = ea_u + e * 8;
            ull a0 = ap[0], a1 = ap[1], a2 = ap[2], a3 = ap[3], a4 = ap[4], a5 = ap[5];
            ull x0 = xs_u[e * 256 + i0], x1 = xs_u[e * 256 + i0 + 1];
            ull t0 = fma2(w0[0], a0, w0[6]);
            t0 = fma2(w0[1], a1, t0); t0 = fma2(w0[2], a2, t0);
            t0 = fma2(w0[3], a3, t0); t0 = fma2(w0[4], a4, t0);
            t0 = fma2(w0[5], a5, t0);
            acc[e] = fma2(x0, relu2(t0), acc[e]);
            ull t1 = fma2(w1[0], a0, w1[6]);
            t1 = fma2(w1[1], a1, t1); t1 = fma2(w1[2], a2, t1);
            t1 = fma2(w1[3], a3, t1); t1 = fma2(w1[4], a4, t1);
            t1 = fma2(w1[5], a5, t1);
            acc[e] = fma2(x1, relu2(t1), acc[e]);
        }
    }

    // deterministic phased cross-warp reduction
    for (int p = 0; p < 8; p++) {
        if (w == p) {
            if (p == 0) {
#pragma unroll
                for (int e = 0; e < ET; e++) red[lane * (ET + 1) + e] = u2f(acc[e]);
            } else {
#pragma unroll
                for (int e = 0; e < ET; e++) {
                    float2 f = u2f(acc[e]);
                    float2 r = red[lane * (ET + 1) + e];
                    red[lane * (ET + 1) + e] = make_float2(r.x + f.x, r.y + f.y);
                }
            }
        }
        __syncthreads();
    }
    for (int idx = tid; idx < ET * 64; idx += 256) {
        int e = idx >> 6, oo = idx & 63, ee = e0 + e;
        if (ee < NE) {
            float2 pr = red[(oo >> 1) * (ET + 1) + e];
            g_msg[ee * OTOT + oc + oo] = (oo & 1) ? pr.y : pr.x;
        }
    }
}

// ---------------- layers 2/3 aggregate + root linear + relu ----------------
template <int L>
__global__ void k_agg23(const float* __restrict__ b) {
    constexpr int OTOT = (L == 3) ? 64 : 256;
    const float* __restrict__ hin = (L == 3) ? g_h2 : g_h1;
    const float* __restrict__ lt  = (L == 3) ? g_l3t : g_l2t;
    float* __restrict__ hout      = (L == 3) ? g_h3 : g_h2;

    __shared__ float hn[256];
    int n = blockIdx.x, o = threadIdx.x;
    for (int i = o; i < 256; i += OTOT) hn[i] = hin[n * 256 + i];
    __syncthreads();

    int j0 = g_off[n], j1 = g_off[n + 1];
    float acc = 0.f;
    for (int j = j0; j < j1; j++) acc += g_msg[g_perm[j] * OTOT + o];

    float l0 = b[o], l1 = 0.f, l2v = 0.f, l3v = 0.f;
#pragma unroll 4
    for (int i = 0; i < 256; i += 4) {
        l0  = fmaf(hn[i],     lt[(i)     * OTOT + o], l0);
        l1  = fmaf(hn[i + 1], lt[(i + 1) * OTOT + o], l1);
        l2v = fmaf(hn[i + 2], lt[(i + 2) * OTOT + o], l2v);
        l3v = fmaf(hn[i + 3], lt[(i + 3) * OTOT + o], l3v);
    }
    hout[n * OTOT + o] = fmaxf(fmaf(acc, g_inv[n], (l0 + l1) + (l2v + l3v)), 0.f);
}

// ---------------- CBT ----------------
__global__ void k_cbt(float* __restrict__ out) {
    int p = blockIdx.x, a = p / NN, bb = p % NN, c = threadIdx.x;
    float d = fabsf(g_h3[a * 64 + c] - g_h3[bb * 64 + c]) +
              fabsf(g_h3[a * 64 + c + 32] - g_h3[bb * 64 + c + 32]);
#pragma unroll
    for (int s = 16; s; s >>= 1) d += __shfl_xor_sync(0xffffffffu, d, s);
    if (c == 0) out[p] = d;
}

// ---------------- launch ----------------
extern "C" void kernel_launch(void* const* d_in, const int* in_sizes, int n_in,
                              void* d_out, int out_size) {
    const float* x   = (const float*)d_in[0];
    const float* ea  = (const float*)d_in[1];
    const int*   ei  = (const int*)d_in[2];
    const float* n1w = (const float*)d_in[3];
    const float* n1b = (const float*)d_in[4];
    const float* l1w = (const float*)d_in[5];
    const float* b1  = (const float*)d_in[6];
    const float* n2w = (const float*)d_in[7];
    const float* n2b = (const float*)d_in[8];
    const float* l2w = (const float*)d_in[9];
    const float* b2  = (const float*)d_in[10];
    const float* n3w = (const float*)d_in[11];
    const float* n3b = (const float*)d_in[12];
    const float* l3w = (const float*)d_in[13];
    const float* b3  = (const float*)d_in[14];
    float* out = (float*)d_out;
    (void)in_sizes; (void)n_in; (void)out_size;

    k_setup<<<B_ALL, 256>>>(x, ea, ei, n1w, n1b, n2w, n2b, n3w, n3b, l2w, l3w);
    k_agg1<<<NN, 256>>>(x, l1w, b1);
    k_msg<16, 2><<<dim3((NE + 15) / 16, 4), 256>>>(ei);
    k_agg23<2><<<NN, 256>>>(b2);
    k_msg<8, 3><<<dim3((NE + 7) / 8, 1), 256>>>(ei);
    k_agg23<3><<<NN, 64>>>(b3);
    k_cbt<<<NN * NN, 32>>>(out);
}

// round 4
// speedup vs baseline: 1.0240x; 1.0240x over previous
#include <cuda_runtime.h>

#define NN 35
#define NE 1190
typedef unsigned long long ull;

// ---------------- scratch ----------------
__device__ __align__(16) float g_h1[NN * 256];
__device__ __align__(16) float g_h2[NN * 256];
__device__ __align__(16) float g_h3[NN * 64];
__device__ __align__(16) float g_msg[NE * 256];        // l1 msgs, then l2 msgs
__device__ __align__(16) float g_m3[2][NE * 64];       // l3 partial msgs (i-halves)
__device__ __align__(16) float g_w2q[256 * 7 * 256];   // [i][v(6w+bias)][o]
__device__ __align__(16) float g_w3q[256 * 7 * 64];
__device__ __align__(16) float g_l2t[256 * 256];       // lin2_w^T [i][o]
__device__ __align__(16) float g_l3t[256 * 64];
__device__ __align__(16) float g_ea8[NE * 8];
__device__ int   g_perm[NE];
__device__ int   g_off[NN + 1];
__device__ float g_inv[NN];

// ---------------- f32x2 helpers ----------------
__device__ __forceinline__ ull fma2(ull a, ull b, ull c) {
    ull d; asm("fma.rn.f32x2 %0, %1, %2, %3;" : "=l"(d) : "l"(a), "l"(b), "l"(c));
    return d;
}
__device__ __forceinline__ ull relu2(ull t) {
    unsigned lo, hi;
    asm("mov.b64 {%0, %1}, %2;" : "=r"(lo), "=r"(hi) : "l"(t));
    float fl = fmaxf(__uint_as_float(lo), 0.f);
    float fh = fmaxf(__uint_as_float(hi), 0.f);
    ull r;
    asm("mov.b64 %0, {%1, %2};" : "=l"(r) : "r"(__float_as_uint(fl)), "r"(__float_as_uint(fh)));
    return r;
}
__device__ __forceinline__ float2 u2f(ull t) {
    unsigned lo, hi;
    asm("mov.b64 {%0, %1}, %2;" : "=r"(lo), "=r"(hi) : "l"(t));
    return make_float2(__uint_as_float(lo), __uint_as_float(hi));
}

// ---------------- fused setup ----------------
#define B_L1   75
#define B_P2   (B_L1 + 256)
#define B_P3   (B_P2 + 16)
#define B_T2   (B_P3 + 64)
#define B_T3   (B_T2 + 16)
#define B_EA   (B_T3 + 5)
#define B_ALL  (B_EA + 1)

__global__ void __launch_bounds__(256) k_setup(
    const float* __restrict__ x,  const float* __restrict__ ea,
    const int* __restrict__ eidx,
    const float* __restrict__ n1w, const float* __restrict__ n1b,
    const float* __restrict__ n2w, const float* __restrict__ n2b,
    const float* __restrict__ n3w, const float* __restrict__ n3b,
    const float* __restrict__ l2w, const float* __restrict__ l3w)
{
    __shared__ __align__(16) char smbuf[8192];
    int b = blockIdx.x, tid = threadIdx.x;

    if (b < B_L1) {                                      // layer-1 messages (c_in=1)
        int e0 = b * 16, o = tid;
        float w[6];
#pragma unroll
        for (int v = 0; v < 6; v++) w[v] = n1w[o * 6 + v];
        float bb = n1b[o];
#pragma unroll
        for (int k = 0; k < 16; k++) {
            int e = e0 + k;
            if (e < NE) {
                float t = bb;
#pragma unroll
                for (int v = 0; v < 6; v++) t = fmaf(w[v], ea[e * 6 + v], t);
                g_msg[e * 256 + o] = x[eidx[e]] * fmaxf(t, 0.f);
            }
        }
    } else if (b < B_P2) {                               // pack nn2
        int i = b - B_L1, o = tid, io = i * 256 + o;
#pragma unroll
        for (int v = 0; v < 6; v++) g_w2q[(i * 7 + v) * 256 + o] = n2w[io * 6 + v];
        g_w2q[(i * 7 + 6) * 256 + o] = n2b[io];
    } else if (b < B_P3) {                               // pack nn3
        int rb = b - B_P2;
#pragma unroll
        for (int r = 0; r < 4; r++) {
            int i = rb * 16 + r * 4 + (tid >> 6), o = tid & 63, io = i * 64 + o;
#pragma unroll
            for (int v = 0; v < 6; v++) g_w3q[(i * 7 + v) * 64 + o] = n3w[io * 6 + v];
            g_w3q[(i * 7 + 6) * 64 + o] = n3b[io];
        }
    } else if (b < B_T2) {                               // transpose lin2
        float* tile = (float*)smbuf;
        int rb = b - B_P3, bo = (rb & 7) * 32, bi = (rb >> 3) * 32;
        int tx = tid & 31, ty = tid >> 5;
#pragma unroll
        for (int r = 0; r < 4; r++)
            tile[(ty + r * 8) * 33 + tx] = l2w[(bo + ty + r * 8) * 256 + bi + tx];
        __syncthreads();
#pragma unroll
        for (int r = 0; r < 4; r++)
            g_l2t[(bi + ty + r * 8) * 256 + bo + tx] = tile[tx * 33 + ty + r * 8];
    } else if (b < B_T3) {                               // transpose lin3
        float* tile = (float*)smbuf;
        int rb = b - B_T2, bo = (rb & 1) * 32, bi = (rb >> 1) * 32;
        int tx = tid & 31, ty = tid >> 5;
#pragma unroll
        for (int r = 0; r < 4; r++)
            tile[(ty + r * 8) * 33 + tx] = l3w[(bo + ty + r * 8) * 256 + bi + tx];
        __syncthreads();
#pragma unroll
        for (int r = 0; r < 4; r++)
            g_l3t[(bi + ty + r * 8) * 64 + bo + tx] = tile[tx * 33 + ty + r * 8];
    } else if (b < B_EA) {                               // pad edge attrs
        int rb = b - B_T3;
        for (int idx = rb * 256 + tid; idx < NE * 8; idx += 5 * 256) {
            int e = idx >> 3, v = idx & 7;
            g_ea8[idx] = (v < 6) ? ea[e * 6 + v] : 0.f;
        }
    } else {                                             // deterministic CSR by dst
        int* s_dst = (int*)smbuf;
        int* s_cnt = s_dst + NE;
        int* s_off = s_cnt + 7 * NN;
        for (int e = tid; e < NE; e += 256) s_dst[e] = eidx[NE + e];
        __syncthreads();
        if (tid < 7 * NN) {
            int c = tid / NN, n = tid % NN;
            int lo = c * 170, cnt = 0;
            for (int e = lo; e < lo + 170; e++) cnt += (s_dst[e] == n);
            s_cnt[c * NN + n] = cnt;
        }
        __syncthreads();
        if (tid == 0) {
            int off = 0;
            for (int n = 0; n < NN; n++) {
                s_off[n] = off;
                for (int c = 0; c < 7; c++) {
                    int t = s_cnt[c * NN + n];
                    s_cnt[c * NN + n] = off;
                    off += t;
                }
            }
            s_off[NN] = off;
        }
        __syncthreads();
        if (tid < 7 * NN) {
            int c = tid / NN, n = tid % NN;
            int lo = c * 170, p = s_cnt[c * NN + n];
            for (int e = lo; e < lo + 170; e++)
                if (s_dst[e] == n) g_perm[p++] = e;
        }
        if (tid <= NN) g_off[tid] = s_off[tid];
        if (tid < NN) g_inv[tid] = 1.0f / (float)max(s_off[tid + 1] - s_off[tid], 1);
    }
}

// ---------------- layer-1 aggregate: grid (35,4), 256 thr = 64 o x 4 edge-groups ----
__global__ void __launch_bounds__(256) k_agg1f(const float* __restrict__ x,
                                               const float* __restrict__ lw,
                                               const float* __restrict__ b) {
    __shared__ float sred[4][64];
    int n = blockIdx.x, o = blockIdx.y * 64 + (threadIdx.x & 63), g = threadIdx.x >> 6;
    int j0 = g_off[n], j1 = g_off[n + 1];
    float acc = 0.f;
    for (int j = j0 + g; j < j1; j += 4) acc += g_msg[g_perm[j] * 256 + o];
    sred[g][threadIdx.x & 63] = acc;
    __syncthreads();
    if (threadIdx.x < 64) {
        int oo = blockIdx.y * 64 + threadIdx.x;
        float tot = sred[0][threadIdx.x] + sred[1][threadIdx.x] +
                    sred[2][threadIdx.x] + sred[3][threadIdx.x];
        g_h1[n * 256 + oo] = fmaxf(fmaf(tot, g_inv[n], fmaf(x[n], lw[oo], b[oo])), 0.f);
    }
}

// ---------------- heavy message kernel: edge-parallel, packed f32x2 ----------------
// L=2: grid (149,4), blockIdx.y = o-chunk; warp w covers i in [32w,32w+32).
// L=3: grid (149,2), blockIdx.y = i-half; warp w covers i in [ih*128+16w, +16).
template <int ET, int L>
__global__ void __launch_bounds__(256, 2) k_msg(const int* __restrict__ eidx) {
    constexpr int OTOT = (L == 3) ? 64 : 256;
    constexpr int OP = OTOT / 2;
    constexpr int NITB = (L == 3) ? 8 : 16;
    constexpr int IW = (L == 3) ? 128 : 256;             // i-range width in this block
    const float* __restrict__ wq  = (L == 3) ? g_w3q : g_w2q;
    const float* __restrict__ hin = (L == 3) ? g_h2 : g_h1;

    __shared__ float2 xs_sm[ET * IW];
    __shared__ float2 ea_sm[ET * 8];
    __shared__ float2 red[32 * (ET + 1)];
    __shared__ int    s_src[ET];

    int tid = threadIdx.x, lane = tid & 31, w = tid >> 5;
    int e0 = blockIdx.x * ET;
    int oc = (L == 3) ? 0 : blockIdx.y * 64;
    int ih = (L == 3) ? blockIdx.y : 0;
    int op = (oc >> 1) + lane;
    float* __restrict__ msgout = (L == 3) ? g_m3[ih] : g_msg;

    if (tid < ET) {
        int ee = e0 + tid; if (ee >= NE) ee = NE - 1;
        s_src[tid] = eidx[ee];
    }
    __syncthreads();
    for (int idx = tid; idx < ET * 8; idx += 256) {
        int e = idx >> 3, ee = e0 + e; if (ee >= NE) ee = NE - 1;
        float a = g_ea8[ee * 8 + (idx & 7)];
        ea_sm[idx] = make_float2(a, a);
    }
    for (int idx = tid; idx < ET * IW; idx += 256) {
        int e = idx / IW, c = ih * 128 + (idx % IW);
        float v = hin[s_src[e] * 256 + c];
        xs_sm[idx] = make_float2(v, v);
    }
    __syncthreads();

    const ull* wq2  = (const ull*)wq;
    const ull* xs_u = (const ull*)xs_sm;
    const ull* ea_u = (const ull*)ea_sm;

    ull acc[ET];
#pragma unroll
    for (int e = 0; e < ET; e++) acc[e] = 0ull;

#pragma unroll 1
    for (int itb = 0; itb < NITB; itb++) {
        int iloc = w * (NITB * 2) + itb * 2;             // local i within block's range
        int ig = ih * 128 + iloc;                        // global i (weight index)
        ull w0[7], w1[7];
        size_t b0 = (size_t)(ig * 7) * OP + op;
        size_t b1 = (size_t)((ig + 1) * 7) * OP + op;
#pragma unroll
        for (int v = 0; v < 7; v++) { w0[v] = wq2[b0 + v * OP]; w1[v] = wq2[b1 + v * OP]; }
#pragma unroll
        for (int e = 0; e < ET; e++) {
            const ull* ap = ea_u + e * 8;
            ull a0 = ap[0], a1 = ap[1], a2 = ap[2], a3 = ap[3], a4 = ap[4], a5 = ap[5];
            ull x0 = xs_u[e * IW + iloc], x1 = xs_u[e * IW + iloc + 1];
            ull t0 = fma2(w0[0], a0, w0[6]);
            t0 = fma2(w0[1], a1, t0); t0 = fma2(w0[2], a2, t0);
            t0 = fma2(w0[3], a3, t0); t0 = fma2(w0[4], a4, t0);
            t0 = fma2(w0[5], a5, t0);
            acc[e] = fma2(x0, relu2(t0), acc[e]);
            ull t1 = fma2(w1[0], a0, w1[6]);
            t1 = fma2(w1[1], a1, t1); t1 = fma2(w1[2], a2, t1);
            t1 = fma2(w1[3], a3, t1); t1 = fma2(w1[4], a4, t1);
            t1 = fma2(w1[5], a5, t1);
            acc[e] = fma2(x1, relu2(t1), acc[e]);
        }
    }

    // deterministic phased cross-warp reduction over i-subranges
    for (int p = 0; p < 8; p++) {
        if (w == p) {
            if (p == 0) {
#pragma unroll
                for (int e = 0; e < ET; e++) red[lane * (ET + 1) + e] = u2f(acc[e]);
            } else {
#pragma unroll
                for (int e = 0; e < ET; e++) {
                    float2 f = u2f(acc[e]);
                    float2 r = red[lane * (ET + 1) + e];
                    red[lane * (ET + 1) + e] = make_float2(r.x + f.x, r.y + f.y);
                }
            }
        }
        __syncthreads();
    }
    for (int idx = tid; idx < ET * 64; idx += 256) {
        int e = idx >> 6, oo = idx & 63, ee = e0 + e;
        if (ee < NE && oo < OTOT) {
            float2 pr = red[(oo >> 1) * (ET + 1) + e];
            msgout[ee * OTOT + oc + oo] = (oo & 1) ? pr.y : pr.x;
        }
    }
}

// ---------------- layers 2/3 aggregate + root linear + relu (parallel) ----------------
// grid (35, OTOT/64), 256 thr = 64 o x 4 groups (edge-groups and i-quarters)
template <int L>
__global__ void __launch_bounds__(256) k_aggf(const float* __restrict__ b) {
    constexpr int OTOT = (L == 3) ? 64 : 256;
    const float* __restrict__ hin = (L == 3) ? g_h2 : g_h1;
    const float* __restrict__ lt  = (L == 3) ? g_l3t : g_l2t;
    float* __restrict__ hout      = (L == 3) ? g_h3 : g_h2;

    __shared__ float hn[256];
    __shared__ float2 sred[4][64];
    int n = blockIdx.x, o64 = threadIdx.x & 63, g = threadIdx.x >> 6;
    int oc = blockIdx.y * 64, o = oc + o64;

    for (int i = threadIdx.x; i < 256; i += 256) hn[i] = hin[n * 256 + i];
    __syncthreads();

    int j0 = g_off[n], j1 = g_off[n + 1];
    float macc = 0.f;
    if (L == 3) {
        for (int j = j0 + g; j < j1; j += 4) {
            int e = g_perm[j];
            macc += g_m3[0][e * 64 + o] + g_m3[1][e * 64 + o];
        }
    } else {
        for (int j = j0 + g; j < j1; j += 4) macc += g_msg[g_perm[j] * OTOT + o];
    }

    float lin = 0.f;
    int ib = g * 64;
#pragma unroll 8
    for (int i = 0; i < 64; i++) lin = fmaf(hn[ib + i], lt[(ib + i) * OTOT + o], lin);

    sred[g][o64] = make_float2(macc, lin);
    __syncthreads();
    if (threadIdx.x < 64) {
        float2 r0 = sred[0][threadIdx.x], r1 = sred[1][threadIdx.x];
        float2 r2 = sred[2][threadIdx.x], r3 = sred[3][threadIdx.x];
        float m = (r0.x + r1.x) + (r2.x + r3.x);
        float l = (r0.y + r1.y) + (r2.y + r3.y);
        int oo = oc + threadIdx.x;
        hout[n * OTOT + oo] = fmaxf(fmaf(m, g_inv[n], l + b[oo]), 0.f);
    }
}

// ---------------- CBT ----------------
__global__ void k_cbt(float* __restrict__ out) {
    int p = blockIdx.x, a = p / NN, bb = p % NN, c = threadIdx.x;
    float d = fabsf(g_h3[a * 64 + c] - g_h3[bb * 64 + c]) +
              fabsf(g_h3[a * 64 + c + 32] - g_h3[bb * 64 + c + 32]);
#pragma unroll
    for (int s = 16; s; s >>= 1) d += __shfl_xor_sync(0xffffffffu, d, s);
    if (c == 0) out[p] = d;
}

// ---------------- launch ----------------
extern "C" void kernel_launch(void* const* d_in, const int* in_sizes, int n_in,
                              void* d_out, int out_size) {
    const float* x   = (const float*)d_in[0];
    const float* ea  = (const float*)d_in[1];
    const int*   ei  = (const int*)d_in[2];
    const float* n1w = (const float*)d_in[3];
    const float* n1b = (const float*)d_in[4];
    const float* l1w = (const float*)d_in[5];
    const float* b1  = (const float*)d_in[6];
    const float* n2w = (const float*)d_in[7];
    const float* n2b = (const float*)d_in[8];
    const float* l2w = (const float*)d_in[9];
    const float* b2  = (const float*)d_in[10];
    const float* n3w = (const float*)d_in[11];
    const float* n3b = (const float*)d_in[12];
    const float* l3w = (const float*)d_in[13];
    const float* b3  = (const float*)d_in[14];
    float* out = (float*)d_out;
    (void)in_sizes; (void)n_in; (void)out_size;

    k_setup<<<B_ALL, 256>>>(x, ea, ei, n1w, n1b, n2w, n2b, n3w, n3b, l2w, l3w);
    k_agg1f<<<dim3(NN, 4), 256>>>(x, l1w, b1);
    k_msg<8, 2><<<dim3((NE + 7) / 8, 4), 256>>>(ei);
    k_aggf<2><<<dim3(NN, 4), 256>>>(b2);
    k_msg<8, 3><<<dim3((NE + 7) / 8, 2), 256>>>(ei);
    k_aggf<3><<<dim3(NN, 1), 256>>>(b3);
    k_cbt<<<NN * NN, 32>>>(out);
}